// round 1
// baseline (speedup 1.0000x reference)
#include <cuda_runtime.h>
#include <cuda_bf16.h>

#define NBLK 1024
#define NTHR 256

__device__ float g_partial[NBLK];

__device__ __forceinline__ float fast_log(float x) {
    float r; asm("lg2.approx.f32 %0, %1;" : "=f"(r) : "f"(x));
    return r * 0.69314718055994531f;
}
__device__ __forceinline__ float fast_exp(float x) {
    float r; asm("ex2.approx.f32 %0, %1;" : "=f"(r) : "f"(x * 1.44269504088896341f));
    return r;
}
__device__ __forceinline__ float fast_rcp(float x) {
    float r; asm("rcp.approx.f32 %0, %1;" : "=f"(r) : "f"(x));
    return r;
}
__device__ __forceinline__ float fast_sqrt(float x) {
    float r; asm("sqrt.approx.f32 %0, %1;" : "=f"(r) : "f"(x));
    return r;
}

__device__ __forceinline__ float superloss_elem(float p, float t) {
    const float TAU = 1.5f;
    const float INV_LAM = 1.0f / 0.9f;
    const float E = 2.71828182845904523f;
    const float NEG_2_OVER_E = -0.73575888234288465f;

    // BCE (clamps inactive for these inputs but kept for parity)
    float lp  = fmaxf(fast_log(p), -100.0f);
    float l1p = fmaxf(fast_log(1.0f - p), -100.0f);
    float l = -(t * lp + (1.0f - t) * l1p);

    float lmt = l - TAU;
    float y = 0.5f * fmaxf(NEG_2_OVER_E, lmt * INV_LAM);   // y >= -1/e

    // Init: branch-point series for y<0, log1p otherwise (both predicated)
    float arg  = 2.0f * fmaf(E, y, 1.0f);
    float wneg = fast_sqrt(fmaxf(arg, 0.0f)) - 1.0f;
    float wpos = fast_log(1.0f + y);
    float w = (y < 0.0f) ? wneg : wpos;

    // Halley, single-division form:
    // delta = 2*f*(w+1) / (2*e^w*(w+1)^2 - (w+2)*f)
#pragma unroll
    for (int it = 0; it < 3; ++it) {
        float ew  = fast_exp(w);
        float f   = fmaf(w, ew, -y);
        float wp1 = w + 1.0f;
        float num = 2.0f * f * wp1;
        float den = fmaf(2.0f * ew, wp1 * wp1, -(w + 2.0f) * f);
        w = w - num * fast_rcp(den + 1e-12f);
    }

    float sigma = fast_exp(-w);
    return fmaf(lmt, sigma, 0.9f * w * w);
}

__global__ void __launch_bounds__(NTHR)
superloss_main(const float* __restrict__ logits,
               const float* __restrict__ targets,
               int n) {
    int tid = threadIdx.x;
    int gtid = blockIdx.x * NTHR + tid;
    int nv = n >> 2;                     // float4 count
    int stride = NBLK * NTHR;

    float acc = 0.0f;
    for (int i = gtid; i < nv; i += stride) {
        float4 p4 = reinterpret_cast<const float4*>(logits)[i];
        float4 t4 = reinterpret_cast<const float4*>(targets)[i];
        acc += superloss_elem(p4.x, t4.x);
        acc += superloss_elem(p4.y, t4.y);
        acc += superloss_elem(p4.z, t4.z);
        acc += superloss_elem(p4.w, t4.w);
    }
    // scalar tail (n not multiple of 4)
    int tail_start = nv << 2;
    for (int i = tail_start + gtid; i < n; i += stride)
        acc += superloss_elem(logits[i], targets[i]);

    __shared__ float s[NTHR];
    s[tid] = acc;
    __syncthreads();
#pragma unroll
    for (int o = NTHR / 2; o > 0; o >>= 1) {
        if (tid < o) s[tid] += s[tid + o];
        __syncthreads();
    }
    if (tid == 0) g_partial[blockIdx.x] = s[0];
}

__global__ void __launch_bounds__(NBLK)
superloss_reduce(float* out) {
    int tid = threadIdx.x;
    __shared__ float s[NBLK];
    s[tid] = g_partial[tid];
    __syncthreads();
#pragma unroll
    for (int o = NBLK / 2; o > 0; o >>= 1) {
        if (tid < o) s[tid] += s[tid + o];
        __syncthreads();
    }
    if (tid == 0) out[0] = s[0] * (1.0f / 32.0f);   // / BATCH_SIZE
}

extern "C" void kernel_launch(void* const* d_in, const int* in_sizes, int n_in,
                              void* d_out, int out_size) {
    const float* logits  = (const float*)d_in[0];
    const float* targets = (const float*)d_in[1];
    float* out = (float*)d_out;
    int n = in_sizes[0];

    superloss_main<<<NBLK, NTHR>>>(logits, targets, n);
    superloss_reduce<<<1, NBLK>>>(out);
}

// round 2
// speedup vs baseline: 1.4968x; 1.4968x over previous
#include <cuda_runtime.h>
#include <cuda_bf16.h>

#define NBLK 1024
#define NTHR 256

__device__ float g_partial[NBLK];
__device__ unsigned int g_count = 0;

__device__ __forceinline__ float fast_log(float x) {
    float r; asm("lg2.approx.f32 %0, %1;" : "=f"(r) : "f"(x));
    return r * 0.69314718055994531f;
}
__device__ __forceinline__ float fast_exp(float x) {
    float r; asm("ex2.approx.f32 %0, %1;" : "=f"(r) : "f"(x * 1.44269504088896341f));
    return r;
}
__device__ __forceinline__ float fast_rcp(float x) {
    float r; asm("rcp.approx.f32 %0, %1;" : "=f"(r) : "f"(x));
    return r;
}
__device__ __forceinline__ float fast_sqrt(float x) {
    float r; asm("sqrt.approx.f32 %0, %1;" : "=f"(r) : "f"(x));
    return r;
}

__device__ __forceinline__ float superloss_elem(float p, float t) {
    const float TAU = 1.5f;
    const float INV_LAM = 1.0f / 0.9f;
    const float E = 2.71828182845904523f;
    const float NEG_2_OVER_E = -0.73575888234288465f;

    // BCE: l = t*(log(1-p) - log(p)) - log(1-p)
    float lp  = fmaxf(fast_log(p), -100.0f);          // MUFU 1
    float l1p = fmaxf(fast_log(1.0f - p), -100.0f);   // MUFU 2
    float l = fmaf(t, l1p - lp, -l1p);

    float lmt = l - TAU;
    float y = 0.5f * fmaxf(NEG_2_OVER_E, lmt * INV_LAM);   // y >= -1/e

    // Init: near-branch series (to rho^3) for y < -0.22, log1p otherwise.
    float rho2 = 2.0f * fmaf(E, y, 1.0f);                  // = rho^2 >= 0
    float rho  = fast_sqrt(fmaxf(rho2, 0.0f));             // MUFU 3
    // w_ser = -1 + rho - rho^2/3 + (11/72) rho^3
    float wser = fmaf(rho * rho2, 0.15277777778f,
                      fmaf(rho2, -0.33333333333f, rho - 1.0f));
    float wlog = fast_log(1.0f + y);                       // MUFU 4
    float w = (y < -0.22f) ? wser : wlog;

    // One Halley step (single division form):
    // delta = 2*f*(w+1) / (2*e^w*(w+1)^2 - (w+2)*f)
    float ew  = fast_exp(w);                               // MUFU 5
    float f   = fmaf(w, ew, -y);
    float wp1 = w + 1.0f;
    float num = 2.0f * f * wp1;
    float den = fmaf(2.0f * ew, wp1 * wp1, -(w + 2.0f) * f);
    w = w - num * fast_rcp(den + 1e-12f);                  // MUFU 6

    float sigma = fast_exp(-w);                            // MUFU 7
    return fmaf(lmt, sigma, 0.9f * w * w);
}

__global__ void __launch_bounds__(NTHR)
superloss_fused(const float* __restrict__ logits,
                const float* __restrict__ targets,
                float* __restrict__ out,
                int n) {
    int tid = threadIdx.x;
    int gtid = blockIdx.x * NTHR + tid;
    int nv = n >> 2;
    int stride = NBLK * NTHR;

    float acc = 0.0f;
    for (int i = gtid; i < nv; i += stride) {
        float4 p4 = reinterpret_cast<const float4*>(logits)[i];
        float4 t4 = reinterpret_cast<const float4*>(targets)[i];
        acc += superloss_elem(p4.x, t4.x);
        acc += superloss_elem(p4.y, t4.y);
        acc += superloss_elem(p4.z, t4.z);
        acc += superloss_elem(p4.w, t4.w);
    }
    int tail_start = nv << 2;
    for (int i = tail_start + gtid; i < n; i += stride)
        acc += superloss_elem(logits[i], targets[i]);

    __shared__ float s[NTHR];
    __shared__ bool is_last;
    s[tid] = acc;
    __syncthreads();
#pragma unroll
    for (int o = NTHR / 2; o > 0; o >>= 1) {
        if (tid < o) s[tid] += s[tid + o];
        __syncthreads();
    }
    if (tid == 0) {
        g_partial[blockIdx.x] = s[0];
        __threadfence();
        // atomicInc wraps to 0 at NBLK-1 -> counter auto-resets for next replay
        unsigned int prev = atomicInc(&g_count, NBLK - 1);
        is_last = (prev == NBLK - 1);
    }
    __syncthreads();

    if (is_last) {
        __threadfence();
        volatile float* gp = g_partial;
        float a = 0.0f;
        // fixed order: each thread sums indices tid, tid+NTHR, ... -> deterministic
#pragma unroll
        for (int j = tid; j < NBLK; j += NTHR) a += gp[j];
        s[tid] = a;
        __syncthreads();
#pragma unroll
        for (int o = NTHR / 2; o > 0; o >>= 1) {
            if (tid < o) s[tid] += s[tid + o];
            __syncthreads();
        }
        if (tid == 0) out[0] = s[0] * (1.0f / 32.0f);
    }
}

extern "C" void kernel_launch(void* const* d_in, const int* in_sizes, int n_in,
                              void* d_out, int out_size) {
    const float* logits  = (const float*)d_in[0];
    const float* targets = (const float*)d_in[1];
    float* out = (float*)d_out;
    int n = in_sizes[0];

    superloss_fused<<<NBLK, NTHR>>>(logits, targets, out, n);
}

// round 3
// speedup vs baseline: 1.7466x; 1.1669x over previous
#include <cuda_runtime.h>
#include <cuda_bf16.h>

#define NBLK 1184   // 148 SMs * 8 blocks -> even occupancy
#define NTHR 256

__device__ float g_partial[NBLK];
__device__ unsigned int g_count = 0;

__device__ __forceinline__ float fast_lg2(float x) {
    float r; asm("lg2.approx.f32 %0, %1;" : "=f"(r) : "f"(x));
    return r;
}
__device__ __forceinline__ float fast_ex2(float x) {
    float r; asm("ex2.approx.f32 %0, %1;" : "=f"(r) : "f"(x));
    return r;
}
__device__ __forceinline__ float fast_rcp(float x) {
    float r; asm("rcp.approx.f32 %0, %1;" : "=f"(r) : "f"(x));
    return r;
}
__device__ __forceinline__ float fast_sqrt(float x) {
    float r; asm("sqrt.approx.f32 %0, %1;" : "=f"(r) : "f"(x));
    return r;
}

__device__ __forceinline__ float superloss_elem(float p, float t) {
    const float LN2     = 0.69314718055994531f;
    const float L2E     = 1.44269504088896341f;
    const float E       = 2.71828182845904523f;
    const float NEG_INV_E = -0.36787944117144233f;
    const float CLAMP_LMT = -0.66218299410859620f;  // 0.9 * (-2/e)

    // BCE in base-2 domain: l = -ln2*(t*lg2(p) + (1-t)*lg2(1-p))
    // (inputs are in (1e-6, 1-1e-6); the -100 clamp can never fire)
    float lp2  = fast_lg2(p);                  // MUFU 1
    float l1p2 = fast_lg2(1.0f - p);           // MUFU 2
    float nl2 = fmaf(t, l1p2 - lp2, -l1p2);    // = l / ln2
    float lmt = fmaf(LN2, nl2, -1.5f);         // l - tau

    // y = max(-1/e, lmt / (2*lam))
    float y = fmaxf(lmt * 0.55555555556f, NEG_INV_E);

    // rho = sqrt(2*(1 + e*y)) in [0, 6.27]
    float rho2 = fmaf(2.0f * E, y, 2.0f);
    float rho  = fast_sqrt(fmaxf(rho2, 0.0f)); // MUFU 3

    // Init: w0 = -1 + rho*h(rho), degree-6 interpolant of (W+1)/rho.
    // Max |w0 - W| ~ 3e-4 over the full range.
    float h = fmaf(rho, 2.72851e-5f, -6.43946e-4f);
    h = fmaf(h, rho,  6.307194e-3f);
    h = fmaf(h, rho, -3.4116882e-2f);
    h = fmaf(h, rho,  0.118663595f);
    h = fmaf(h, rho, -0.322237288f);
    h = fmaf(h, rho,  1.0f);
    float w = fmaf(rho, h, -1.0f);

    // One Halley step (single division): delta = 2f(w+1)/(2e^w(w+1)^2 - (w+2)f)
    float ew  = fast_ex2(w * L2E);             // MUFU 4
    float f   = fmaf(w, ew, -y);
    float wp1 = w + 1.0f;
    float num = (f + f) * wp1;
    float den = fmaf(ew + ew, wp1 * wp1, -(w + 2.0f) * f) + 1e-12f;
    w = fmaf(-num, fast_rcp(den), w);          // MUFU 5

    // Loss via fixed-point identity y*exp(-w) = w:
    //   unclamped: (l-tau)*sigma + lam*w^2 = 2*lam*w + lam*w^2 = 0.9*w*(w+2)
    //   clamped (y=-1/e, w=-1): lmt*e + 0.9
    float loss_u = (0.9f * w) * (w + 2.0f);
    float loss_c = fmaf(lmt, E, 0.9f);
    return (lmt < CLAMP_LMT) ? loss_c : loss_u;
}

__global__ void __launch_bounds__(NTHR)
superloss_fused(const float* __restrict__ logits,
                const float* __restrict__ targets,
                float* __restrict__ out,
                int n) {
    int tid = threadIdx.x;
    int gtid = blockIdx.x * NTHR + tid;
    int nv = n >> 2;
    int stride = NBLK * NTHR;

    float acc = 0.0f;
    for (int i = gtid; i < nv; i += stride) {
        float4 p4 = reinterpret_cast<const float4*>(logits)[i];
        float4 t4 = reinterpret_cast<const float4*>(targets)[i];
        acc += superloss_elem(p4.x, t4.x);
        acc += superloss_elem(p4.y, t4.y);
        acc += superloss_elem(p4.z, t4.z);
        acc += superloss_elem(p4.w, t4.w);
    }
    int tail_start = nv << 2;
    for (int i = tail_start + gtid; i < n; i += stride)
        acc += superloss_elem(logits[i], targets[i]);

    __shared__ float s[NTHR];
    __shared__ bool is_last;
    s[tid] = acc;
    __syncthreads();
#pragma unroll
    for (int o = NTHR / 2; o > 0; o >>= 1) {
        if (tid < o) s[tid] += s[tid + o];
        __syncthreads();
    }
    if (tid == 0) {
        g_partial[blockIdx.x] = s[0];
        __threadfence();
        unsigned int prev = atomicInc(&g_count, NBLK - 1);
        is_last = (prev == NBLK - 1);
    }
    __syncthreads();

    if (is_last) {
        __threadfence();
        volatile float* gp = g_partial;
        float a = 0.0f;
        for (int j = tid; j < NBLK; j += NTHR) a += gp[j];
        s[tid] = a;
        __syncthreads();
#pragma unroll
        for (int o = NTHR / 2; o > 0; o >>= 1) {
            if (tid < o) s[tid] += s[tid + o];
            __syncthreads();
        }
        if (tid == 0) out[0] = s[0] * (1.0f / 32.0f);
    }
}

extern "C" void kernel_launch(void* const* d_in, const int* in_sizes, int n_in,
                              void* d_out, int out_size) {
    const float* logits  = (const float*)d_in[0];
    const float* targets = (const float*)d_in[1];
    float* out = (float*)d_out;
    int n = in_sizes[0];

    superloss_fused<<<NBLK, NTHR>>>(logits, targets, out, n);
}

// round 4
// speedup vs baseline: 1.9494x; 1.1161x over previous
#include <cuda_runtime.h>
#include <cuda_bf16.h>

#define NBLK 1184   // 148 SMs * 8
#define NTHR 256

__device__ float g_partial[NBLK];
__device__ unsigned int g_count = 0;

typedef unsigned long long u64;

__device__ __forceinline__ float fast_lg2(float x) {
    float r; asm("lg2.approx.f32 %0, %1;" : "=f"(r) : "f"(x)); return r;
}
__device__ __forceinline__ float fast_ex2(float x) {
    float r; asm("ex2.approx.f32 %0, %1;" : "=f"(r) : "f"(x)); return r;
}
__device__ __forceinline__ float fast_rcp(float x) {
    float r; asm("rcp.approx.f32 %0, %1;" : "=f"(r) : "f"(x)); return r;
}
__device__ __forceinline__ float fast_sqrt(float x) {
    float r; asm("sqrt.approx.f32 %0, %1;" : "=f"(r) : "f"(x)); return r;
}

// ---- packed f32x2 helpers (sm_103) ----
__device__ __forceinline__ u64 pk2(float a, float b) {
    u64 r; asm("mov.b64 %0, {%1, %2};" : "=l"(r) : "f"(a), "f"(b)); return r;
}
__device__ __forceinline__ void upk2(float& a, float& b, u64 v) {
    asm("mov.b64 {%0, %1}, %2;" : "=f"(a), "=f"(b) : "l"(v));
}
__device__ __forceinline__ u64 f2fma(u64 a, u64 b, u64 c) {
    u64 r; asm("fma.rn.f32x2 %0, %1, %2, %3;" : "=l"(r) : "l"(a), "l"(b), "l"(c)); return r;
}
__device__ __forceinline__ u64 f2mul(u64 a, u64 b) {
    u64 r; asm("mul.rn.f32x2 %0, %1, %2;" : "=l"(r) : "l"(a), "l"(b)); return r;
}
__device__ __forceinline__ u64 f2add(u64 a, u64 b) {
    u64 r; asm("add.rn.f32x2 %0, %1, %2;" : "=l"(r) : "l"(a), "l"(b)); return r;
}
__device__ __forceinline__ u64 bc(float x) { return pk2(x, x); }

// Process a pair of elements with packed f32x2 math.
__device__ __forceinline__ void superloss_pair(float p0, float p1, float t0, float t1,
                                               float& acc0, float& acc1) {
    const float E = 2.71828182845904523f;
    const float CLAMP_LMT = -0.66218299410859620f;  // 1.8 * (-1/e)

    const u64 C_M1   = bc(-1.0f);
    const u64 C_LN2  = bc(0.69314718055994531f);
    const u64 C_MLN2 = bc(-0.69314718055994531f);
    const u64 C_M15  = bc(-1.5f);
    const u64 C_MI18 = bc(-0.55555555555555556f);
    const u64 C_M2E  = bc(-5.43656365691809047f);   // -2e
    const u64 C_2    = bc(2.0f);
    const u64 C_L2E  = bc(1.44269504088896341f);
    const u64 C_09   = bc(0.9f);
    const u64 C_P6 = bc(2.72851e-5f);
    const u64 C_P5 = bc(-6.43946e-4f);
    const u64 C_P4 = bc(6.307194e-3f);
    const u64 C_P3 = bc(-3.4116882e-2f);
    const u64 C_P2 = bc(0.118663595f);
    const u64 C_P1 = bc(-0.322237288f);
    const u64 C_P0 = bc(1.0f);

    // scalar MUFU logs
    float a0 = fast_lg2(p0),        a1 = fast_lg2(p1);
    float b0 = fast_lg2(1.0f - p0), b1 = fast_lg2(1.0f - p1);

    u64 d_lp  = pk2(a0, a1);
    u64 d_l1p = pk2(b0, b1);
    u64 d_t   = pk2(t0, t1);

    // lmt = l - tau = ln2*(t*(l1p2 - lp2) - l1p2) - 1.5
    u64 d_diff = f2fma(d_lp, C_M1, d_l1p);        // l1p2 - lp2
    u64 d_tl   = f2mul(d_t, C_LN2);
    u64 d_cc   = f2fma(d_l1p, C_MLN2, C_M15);
    u64 d_lmt  = f2fma(d_tl, d_diff, d_cc);

    u64 d_z  = f2mul(d_lmt, C_MI18);              // z = -y
    u64 d_r2 = f2fma(d_z, C_M2E, C_2);            // rho^2 = 2(1 + e*y)

    float r20, r21; upk2(r20, r21, d_r2);
    float s0 = fast_sqrt(fmaxf(r20, 1e-8f));      // rho >= 1e-4 (Newton-safe)
    float s1 = fast_sqrt(fmaxf(r21, 1e-8f));
    u64 d_rho = pk2(s0, s1);

    // degree-6 init: u0 = w0+1 = rho*h(rho)
    u64 h = f2fma(C_P6, d_rho, C_P5);
    h = f2fma(h, d_rho, C_P4);
    h = f2fma(h, d_rho, C_P3);
    h = f2fma(h, d_rho, C_P2);
    h = f2fma(h, d_rho, C_P1);
    h = f2fma(h, d_rho, C_P0);
    u64 d_u = f2mul(d_rho, h);                    // w+1
    u64 d_w = f2add(d_u, C_M1);                   // w

    // one Newton step: w1 = w - (w*e^w - y) / (e^w * (w+1))
    u64 d_wl = f2mul(d_w, C_L2E);
    float wl0, wl1; upk2(wl0, wl1, d_wl);
    float e0 = fast_ex2(wl0), e1 = fast_ex2(wl1);
    u64 d_ew = pk2(e0, e1);

    u64 d_f  = f2fma(d_w, d_ew, d_z);             // w*e^w - y
    u64 d_nu = f2mul(d_u, C_M1);                  // -(w+1)
    u64 d_dn = f2mul(d_ew, d_nu);                 // -e^w*(w+1)  (< 0)
    float dn0, dn1; upk2(dn0, dn1, d_dn);
    float rc0 = fast_rcp(dn0), rc1 = fast_rcp(dn1);
    u64 d_rc = pk2(rc0, rc1);
    u64 d_w1 = f2fma(d_f, d_rc, d_w);             // w - f/(e^w(w+1))

    // loss: unclamped 0.9*w*(w+2); clamped lmt*e + 0.9
    u64 d_wp2 = f2add(d_w1, C_2);
    u64 d_w9  = f2mul(d_w1, C_09);
    u64 d_lu  = f2mul(d_w9, d_wp2);

    float lu0, lu1; upk2(lu0, lu1, d_lu);
    float lm0, lm1; upk2(lm0, lm1, d_lmt);
    float lc0 = fmaf(lm0, E, 0.9f);
    float lc1 = fmaf(lm1, E, 0.9f);
    acc0 += (lm0 < CLAMP_LMT) ? lc0 : lu0;
    acc1 += (lm1 < CLAMP_LMT) ? lc1 : lu1;
}

// scalar fallback for tail elements
__device__ __forceinline__ float superloss_scalar(float p, float t) {
    const float LN2 = 0.69314718055994531f;
    const float L2E = 1.44269504088896341f;
    const float E   = 2.71828182845904523f;
    const float CLAMP_LMT = -0.66218299410859620f;

    float lp2  = fast_lg2(p);
    float l1p2 = fast_lg2(1.0f - p);
    float nl2 = fmaf(t, l1p2 - lp2, -l1p2);
    float lmt = fmaf(LN2, nl2, -1.5f);
    float z = lmt * -0.55555555556f;
    float r2 = fmaf(z, -5.43656365691809f, 2.0f);
    float rho = fast_sqrt(fmaxf(r2, 1e-8f));
    float h = fmaf(rho, 2.72851e-5f, -6.43946e-4f);
    h = fmaf(h, rho,  6.307194e-3f);
    h = fmaf(h, rho, -3.4116882e-2f);
    h = fmaf(h, rho,  0.118663595f);
    h = fmaf(h, rho, -0.322237288f);
    h = fmaf(h, rho,  1.0f);
    float u = rho * h;
    float w = u - 1.0f;
    float ew = fast_ex2(w * L2E);
    float f = fmaf(w, ew, z);
    float w1 = fmaf(f, fast_rcp(-ew * u), w);
    float lu = (0.9f * w1) * (w1 + 2.0f);
    float lc = fmaf(lmt, E, 0.9f);
    return (lmt < CLAMP_LMT) ? lc : lu;
}

__global__ void __launch_bounds__(NTHR)
superloss_fused(const float* __restrict__ logits,
                const float* __restrict__ targets,
                float* __restrict__ out,
                int n) {
    int tid = threadIdx.x;
    int gtid = blockIdx.x * NTHR + tid;
    int nv = n >> 2;
    int stride = NBLK * NTHR;

    float acc0 = 0.0f, acc1 = 0.0f;
    for (int i = gtid; i < nv; i += stride) {
        float4 p4 = reinterpret_cast<const float4*>(logits)[i];
        float4 t4 = reinterpret_cast<const float4*>(targets)[i];
        superloss_pair(p4.x, p4.y, t4.x, t4.y, acc0, acc1);
        superloss_pair(p4.z, p4.w, t4.z, t4.w, acc0, acc1);
    }
    int tail_start = nv << 2;
    for (int i = tail_start + gtid; i < n; i += stride)
        acc0 += superloss_scalar(logits[i], targets[i]);

    float acc = acc0 + acc1;

    __shared__ float s[NTHR];
    __shared__ bool is_last;
    s[tid] = acc;
    __syncthreads();
#pragma unroll
    for (int o = NTHR / 2; o > 0; o >>= 1) {
        if (tid < o) s[tid] += s[tid + o];
        __syncthreads();
    }
    if (tid == 0) {
        g_partial[blockIdx.x] = s[0];
        __threadfence();
        unsigned int prev = atomicInc(&g_count, NBLK - 1);
        is_last = (prev == NBLK - 1);
    }
    __syncthreads();

    if (is_last) {
        __threadfence();
        volatile float* gp = g_partial;
        float a = 0.0f;
        for (int j = tid; j < NBLK; j += NTHR) a += gp[j];
        s[tid] = a;
        __syncthreads();
#pragma unroll
        for (int o = NTHR / 2; o > 0; o >>= 1) {
            if (tid < o) s[tid] += s[tid + o];
            __syncthreads();
        }
        if (tid == 0) out[0] = s[0] * (1.0f / 32.0f);
    }
}

extern "C" void kernel_launch(void* const* d_in, const int* in_sizes, int n_in,
                              void* d_out, int out_size) {
    const float* logits  = (const float*)d_in[0];
    const float* targets = (const float*)d_in[1];
    float* out = (float*)d_out;
    int n = in_sizes[0];

    superloss_fused<<<NBLK, NTHR>>>(logits, targets, out, n);
}